// round 14
// baseline (speedup 1.0000x reference)
#include <cuda_runtime.h>
#include <cuda_bf16.h>
#include <cstdint>

#define EPS_F 0.01f

constexpr int B = 16;
constexpr int H = 1024;
constexpr int W = 1024;

// Full-width tile: 1024 cols x 16 rows per CTA. Block = 512 threads (16 warps).
// Warp w: col segment (w & 7)*128, row half (w >> 3)*8. Thread: 4 cols x 8 rows.
constexpr int TH = 16;
constexpr int THREADS = 512;
constexpr int SH_H = TH + 2;                    // 18 rows
constexpr int SMEM_BYTES = SH_H * W * 4;        // 73728 B (dynamic)
constexpr int F4_PER_ROW = W / 4;               // 256
constexpr int FILL_ITERS = SH_H * F4_PER_ROW / THREADS;  // 9 (exact)

__device__ __forceinline__ float fmax3(float a, float b, float c) {
    return fmaxf(fmaxf(a, b), c);
}

// Read one smem row's 6-wide window: center LDS.128 + shfl halo.
// Full-width rows: segment-boundary halo comes from smem; image edge -> 0.
__device__ __forceinline__ void read_sr(
    const float* __restrict__ sx, int sr, int cb, int lane, float w[6])
{
    const unsigned FULL = 0xFFFFFFFFu;
    const float* rowp = sx + sr * W;
    const float4 ce = *(const float4*)(rowp + cb);
    float lft = __shfl_up_sync(FULL, ce.w, 1);
    float rgt = __shfl_down_sync(FULL, ce.x, 1);
    if (lane == 0)  lft = (cb > 0) ? rowp[cb - 1] : 0.0f;
    if (lane == 31) rgt = (cb + 4 < W) ? rowp[cb + 4] : 0.0f;
    w[0] = lft;
    w[1] = ce.x; w[2] = ce.y; w[3] = ce.z; w[4] = ce.w;
    w[5] = rgt;
}

__global__ __launch_bounds__(THREADS) void detection_head_kernel(
    const float* __restrict__ seg,   // [B, 2, H, W]
    float* __restrict__ out)         // [B*H*W] xnms | [B*2*H*W] seg copy
{
    extern __shared__ float sx[];    // [SH_H][W]

    const int b   = blockIdx.y;
    const int ty0 = blockIdx.x * TH;

    const float* __restrict__ c0 = seg + (size_t)b * 2 * H * W;
    const float* __restrict__ c1 = c0 + (size_t)H * W;
    float* __restrict__ oseg = out + (size_t)B * H * W + (size_t)b * 2 * H * W;

    const int tid  = threadIdx.x;
    const int lane = tid & 31;

    // ---- Fill: x = c1 - c0 - EPS into smem (halo rows 0/17; OOB -> 0, exact:
    // pool is relu'd + zero-floored). Seg copy streamed for interior rows.
    // Each warp reads 512 B contiguous; CTA sweeps whole 4 KB rows. ----
    #pragma unroll
    for (int it = 0; it < FILL_ITERS; it++) {
        const int idx  = tid + it * THREADS;
        const int row  = idx >> 8;               // / F4_PER_ROW (256)
        const int gx   = (idx & 255) * 4;
        const int gy   = ty0 - 1 + row;
        float4 v = make_float4(0.f, 0.f, 0.f, 0.f);
        if ((unsigned)gy < (unsigned)H) {
            const size_t g = (size_t)gy * W + gx;
            const float4 a  = *(const float4*)(c0 + g);
            const float4 bb = *(const float4*)(c1 + g);
            v.x = bb.x - a.x - EPS_F;
            v.y = bb.y - a.y - EPS_F;
            v.z = bb.z - a.z - EPS_F;
            v.w = bb.w - a.w - EPS_F;
            if (row >= 1 && row <= TH) {         // interior: copied exactly once
                __stcs((float4*)(oseg + g), a);
                __stcs((float4*)(oseg + (size_t)H * W + g), bb);
            }
        }
        *(float4*)(sx + row * W + gx) = v;
    }
    __syncthreads();

    // ---- Compute: 8 output rows per thread, rolling 3-row window ----
    const int wid  = tid >> 5;                   // 0..15
    const int cb   = (wid & 7) * 128 + lane * 4; // col base 0..1020
    const int yr0  = (wid >> 3) * 8;             // local output rows yr0..yr0+7

    float w_top[6], w_mid[6];
    read_sr(sx, yr0 + 0, cb, lane, w_top);       // global row ty0+yr0-1
    read_sr(sx, yr0 + 1, cb, lane, w_mid);

    float h3t[4], h3m[4];
    #pragma unroll
    for (int i = 0; i < 4; i++) {
        h3t[i] = fmax3(w_top[i], w_top[i + 1], w_top[i + 2]);
        h3m[i] = fmax3(w_mid[i], w_mid[i + 1], w_mid[i + 2]);
    }

    float* __restrict__ oxn = out + (size_t)b * H * W;
    const int gy0 = ty0 + yr0;

    #pragma unroll
    for (int k = 0; k < 8; k++) {
        float w_bot[6], h3b[4];
        read_sr(sx, yr0 + k + 2, cb, lane, w_bot);
        #pragma unroll
        for (int i = 0; i < 4; i++)
            h3b[i] = fmax3(w_bot[i], w_bot[i + 1], w_bot[i + 2]);

        float4 o;
        float* op = &o.x;
        #pragma unroll
        for (int i = 0; i < 4; i++) {
            float m = fmax3(h3t[i], fmaxf(w_mid[i], w_mid[i + 2]), h3b[i]);
            m = fmaxf(m, 0.0f);
            const float x = w_mid[i + 1];
            op[i] = (x > m) ? x : 0.0f;
        }
        __stcs((float4*)(oxn + (size_t)(gy0 + k) * W + cb), o);

        #pragma unroll
        for (int i = 0; i < 4; i++) { h3t[i] = h3m[i]; h3m[i] = h3b[i]; }
        #pragma unroll
        for (int j = 0; j < 6; j++) w_mid[j] = w_bot[j];
    }
}

extern "C" void kernel_launch(void* const* d_in, const int* in_sizes, int n_in,
                              void* d_out, int out_size)
{
    const float* seg = (const float*)d_in[0];
    float* out = (float*)d_out;

    // Opt-in to >48 KB dynamic shared memory (idempotent host-side call).
    cudaFuncSetAttribute(detection_head_kernel,
                         cudaFuncAttributeMaxDynamicSharedMemorySize, SMEM_BYTES);

    dim3 block(THREADS, 1, 1);
    dim3 grid(H / TH, B, 1);   // 64 x 16 = 1024 CTAs
    detection_head_kernel<<<grid, block, SMEM_BYTES>>>(seg, out);
}

// round 15
// speedup vs baseline: 1.0685x; 1.0685x over previous
#include <cuda_runtime.h>
#include <cuda_bf16.h>
#include <cstdint>

#define EPS_F 0.01f

constexpr int B = 16;
constexpr int H = 1024;
constexpr int W = 1024;

// Tile: 128 cols x 32 rows per CTA. Block 32x8 = 256 threads.
// Each thread computes a 4-wide x 4-high output block. Warp = one thread-row.
constexpr int TX = 32;
constexpr int TY = 8;
constexpr int TILE_W = 128;
constexpr int TILE_H = 32;

// smem: rows ty0-1..ty0+32 (34), cols tx0-4..tx0+131 (136 = 34 float4)
constexpr int SH_H = TILE_H + 2;            // 34
constexpr int SH_W = 136;
constexpr int F4_PER_ROW = SH_W / 4;        // 34
constexpr int FILL_TASKS = SH_H * F4_PER_ROW;  // 1156

__device__ __forceinline__ float fmax3(float a, float b, float c) {
    return fmaxf(fmaxf(a, b), c);
}

// L2 evict_last access policy for input loads (measured best config).
__device__ __forceinline__ uint64_t mk_policy_el() {
    uint64_t pol;
    asm("createpolicy.fractional.L2::evict_last.b64 %0, 1.0;" : "=l"(pol));
    return pol;
}

__device__ __forceinline__ float4 ldg_el(const float* p, uint64_t pol) {
    float4 v;
    asm("ld.global.nc.L2::cache_hint.v4.f32 {%0,%1,%2,%3}, [%4], %5;"
        : "=f"(v.x), "=f"(v.y), "=f"(v.z), "=f"(v.w) : "l"(p), "l"(pol));
    return v;
}

// Read one smem row's 6-wide window for this lane: center LDS.128 + shfl halo.
__device__ __forceinline__ void read_sr(
    const float (*sx)[SH_W], int sr, int lc, int lane, float w[6])
{
    const unsigned FULL = 0xFFFFFFFFu;
    const float4 ce = *(const float4*)&sx[sr][lc + 4];
    float lft = __shfl_up_sync(FULL, ce.w, 1);
    float rgt = __shfl_down_sync(FULL, ce.x, 1);
    if (lane == 0)  lft = sx[sr][3];
    if (lane == 31) rgt = sx[sr][132];
    w[0] = lft;
    w[1] = ce.x; w[2] = ce.y; w[3] = ce.z; w[4] = ce.w;
    w[5] = rgt;
}

__global__ __launch_bounds__(TX * TY) void detection_head_kernel(
    const float* __restrict__ seg,   // [B, 2, H, W]
    float* __restrict__ out)         // [B*H*W] xnms | [B*2*H*W] seg copy
{
    __shared__ float sx[SH_H][SH_W];

    const int b   = blockIdx.z;
    const int ty0 = blockIdx.y * TILE_H;
    const int tx0 = blockIdx.x * TILE_W;

    const float* __restrict__ c0 = seg + (size_t)b * 2 * H * W;
    const float* __restrict__ c1 = c0 + (size_t)H * W;
    float* __restrict__ oseg = out + (size_t)B * H * W + (size_t)b * 2 * H * W;

    const int tid  = threadIdx.y * TX + threadIdx.x;
    const int lane = threadIdx.x;
    const uint64_t pol = mk_policy_el();

    // ---- Fill smem with x = c1 - c0 - EPS (halo -> 0, exact: pool is
    // relu'd + zero-floored) AND stream the seg copy for interior pixels. ----
    #pragma unroll
    for (int idx = tid; idx < FILL_TASKS; idx += TX * TY) {
        const unsigned row = (unsigned)idx / F4_PER_ROW;       // 0..33
        const unsigned col = (unsigned)idx - row * F4_PER_ROW; // 0..33
        const int gy = ty0 - 1 + (int)row;
        const int gx = tx0 - 4 + (int)(col * 4);               // 16B aligned
        float4 v = make_float4(0.f, 0.f, 0.f, 0.f);
        if ((unsigned)gy < (unsigned)H && (unsigned)gx < (unsigned)W) {
            const size_t g = (size_t)gy * W + gx;
            const float4 a  = ldg_el(c0 + g, pol);
            const float4 bb = ldg_el(c1 + g, pol);
            v.x = bb.x - a.x - EPS_F;
            v.y = bb.y - a.y - EPS_F;
            v.z = bb.z - a.z - EPS_F;
            v.w = bb.w - a.w - EPS_F;
            // Interior of this CTA's tile: written exactly once chip-wide.
            if (row >= 1u && row <= (unsigned)TILE_H &&
                col >= 1u && col <= (unsigned)(TILE_W / 4)) {
                __stcs((float4*)(oseg + g), a);
                __stcs((float4*)(oseg + (size_t)H * W + g), bb);
            }
        }
        *(float4*)&sx[row][col * 4] = v;
    }
    __syncthreads();

    // ---- Compute: 4 output rows per thread, rolling 3-row window ----
    const int yr0 = threadIdx.y * 4;      // local row 0..28 (smem rows yr0..yr0+5)
    const int lc  = threadIdx.x * 4;      // local col 0..124

    float w_top[6], w_mid[6];
    read_sr(sx, yr0 + 0, lc, lane, w_top);
    read_sr(sx, yr0 + 1, lc, lane, w_mid);

    float h3t[4], h3m[4];
    #pragma unroll
    for (int i = 0; i < 4; i++) {
        h3t[i] = fmax3(w_top[i], w_top[i + 1], w_top[i + 2]);
        h3m[i] = fmax3(w_mid[i], w_mid[i + 1], w_mid[i + 2]);
    }

    const int gy0 = ty0 + yr0;
    const int gx  = tx0 + lc;
    float* __restrict__ oxn = out + (size_t)b * H * W;

    #pragma unroll
    for (int k = 0; k < 4; k++) {
        float w_bot[6], h3b[4];
        read_sr(sx, yr0 + k + 2, lc, lane, w_bot);
        #pragma unroll
        for (int i = 0; i < 4; i++)
            h3b[i] = fmax3(w_bot[i], w_bot[i + 1], w_bot[i + 2]);

        float4 o;
        float* op = &o.x;
        #pragma unroll
        for (int i = 0; i < 4; i++) {
            float m = fmax3(h3t[i], fmaxf(w_mid[i], w_mid[i + 2]), h3b[i]);
            m = fmaxf(m, 0.0f);
            const float x = w_mid[i + 1];
            op[i] = (x > m) ? x : 0.0f;
        }
        __stcs((float4*)(oxn + (size_t)(gy0 + k) * W + gx), o);

        #pragma unroll
        for (int i = 0; i < 4; i++) { h3t[i] = h3m[i]; h3m[i] = h3b[i]; }
        #pragma unroll
        for (int j = 0; j < 6; j++) w_mid[j] = w_bot[j];
    }
}

extern "C" void kernel_launch(void* const* d_in, const int* in_sizes, int n_in,
                              void* d_out, int out_size)
{
    const float* seg = (const float*)d_in[0];
    float* out = (float*)d_out;

    dim3 block(TX, TY, 1);
    dim3 grid(W / TILE_W, H / TILE_H, B);  // 8 x 32 x 16 = 4096 CTAs
    detection_head_kernel<<<grid, block>>>(seg, out);
}

// round 16
// speedup vs baseline: 1.0734x; 1.0046x over previous
#include <cuda_runtime.h>
#include <cuda_bf16.h>
#include <cstdint>

#define EPS_F 0.01f

constexpr int B = 16;
constexpr int H = 1024;
constexpr int W = 1024;

// Tile: 128 cols x 32 rows per CTA. Block 32x8 = 256 threads.
// Each thread computes a 4-wide x 4-high output block. Warp = one thread-row.
constexpr int TX = 32;
constexpr int TY = 8;
constexpr int TILE_W = 128;
constexpr int TILE_H = 32;

// smem: rows ty0-1..ty0+32 (34), cols tx0-4..tx0+131 (136 = 34 float4)
constexpr int SH_H = TILE_H + 2;            // 34
constexpr int SH_W = 136;
constexpr int F4_PER_ROW = SH_W / 4;        // 34
constexpr int FILL_TASKS = SH_H * F4_PER_ROW;  // 1156

__device__ __forceinline__ float fmax3(float a, float b, float c) {
    return fmaxf(fmaxf(a, b), c);
}

// L2 evict_last access policy for input loads (measured best config).
__device__ __forceinline__ uint64_t mk_policy_el() {
    uint64_t pol;
    asm("createpolicy.fractional.L2::evict_last.b64 %0, 1.0;" : "=l"(pol));
    return pol;
}

__device__ __forceinline__ float4 ldg_el(const float* p, uint64_t pol) {
    float4 v;
    asm("ld.global.nc.L2::cache_hint.v4.f32 {%0,%1,%2,%3}, [%4], %5;"
        : "=f"(v.x), "=f"(v.y), "=f"(v.z), "=f"(v.w) : "l"(p), "l"(pol));
    return v;
}

// Read one smem row's 6-wide window for this lane: center LDS.128 + shfl halo.
__device__ __forceinline__ void read_sr(
    const float (*sx)[SH_W], int sr, int lc, int lane, float w[6])
{
    const unsigned FULL = 0xFFFFFFFFu;
    const float4 ce = *(const float4*)&sx[sr][lc + 4];
    float lft = __shfl_up_sync(FULL, ce.w, 1);
    float rgt = __shfl_down_sync(FULL, ce.x, 1);
    if (lane == 0)  lft = sx[sr][3];
    if (lane == 31) rgt = sx[sr][132];
    w[0] = lft;
    w[1] = ce.x; w[2] = ce.y; w[3] = ce.z; w[4] = ce.w;
    w[5] = rgt;
}

__global__ __launch_bounds__(TX * TY) void detection_head_kernel(
    const float* __restrict__ seg,   // [B, 2, H, W]
    float* __restrict__ out)         // [B*H*W] xnms | [B*2*H*W] seg copy
{
    __shared__ float sx[SH_H][SH_W];

    const int b   = blockIdx.z;
    const int ty0 = blockIdx.y * TILE_H;
    const int tx0 = blockIdx.x * TILE_W;

    const float* __restrict__ c0 = seg + (size_t)b * 2 * H * W;
    const float* __restrict__ c1 = c0 + (size_t)H * W;
    float* __restrict__ oseg = out + (size_t)B * H * W + (size_t)b * 2 * H * W;

    const int tid  = threadIdx.y * TX + threadIdx.x;
    const int lane = threadIdx.x;
    const uint64_t pol = mk_policy_el();

    // ---- Fill smem with x = c1 - c0 - EPS (halo -> 0, exact: pool is
    // relu'd + zero-floored) AND stream the seg copy for interior pixels. ----
    #pragma unroll
    for (int idx = tid; idx < FILL_TASKS; idx += TX * TY) {
        const unsigned row = (unsigned)idx / F4_PER_ROW;       // 0..33
        const unsigned col = (unsigned)idx - row * F4_PER_ROW; // 0..33
        const int gy = ty0 - 1 + (int)row;
        const int gx = tx0 - 4 + (int)(col * 4);               // 16B aligned
        float4 v = make_float4(0.f, 0.f, 0.f, 0.f);
        if ((unsigned)gy < (unsigned)H && (unsigned)gx < (unsigned)W) {
            const size_t g = (size_t)gy * W + gx;
            const float4 a  = ldg_el(c0 + g, pol);
            const float4 bb = ldg_el(c1 + g, pol);
            v.x = bb.x - a.x - EPS_F;
            v.y = bb.y - a.y - EPS_F;
            v.z = bb.z - a.z - EPS_F;
            v.w = bb.w - a.w - EPS_F;
            // Interior of this CTA's tile: written exactly once chip-wide.
            if (row >= 1u && row <= (unsigned)TILE_H &&
                col >= 1u && col <= (unsigned)(TILE_W / 4)) {
                __stcs((float4*)(oseg + g), a);
                __stcs((float4*)(oseg + (size_t)H * W + g), bb);
            }
        }
        *(float4*)&sx[row][col * 4] = v;
    }
    __syncthreads();

    // ---- Compute: 4 output rows per thread, rolling 3-row window ----
    const int yr0 = threadIdx.y * 4;      // local row 0..28 (smem rows yr0..yr0+5)
    const int lc  = threadIdx.x * 4;      // local col 0..124

    float w_top[6], w_mid[6];
    read_sr(sx, yr0 + 0, lc, lane, w_top);
    read_sr(sx, yr0 + 1, lc, lane, w_mid);

    float h3t[4], h3m[4];
    #pragma unroll
    for (int i = 0; i < 4; i++) {
        h3t[i] = fmax3(w_top[i], w_top[i + 1], w_top[i + 2]);
        h3m[i] = fmax3(w_mid[i], w_mid[i + 1], w_mid[i + 2]);
    }

    const int gy0 = ty0 + yr0;
    const int gx  = tx0 + lc;
    float* __restrict__ oxn = out + (size_t)b * H * W;

    #pragma unroll
    for (int k = 0; k < 4; k++) {
        float w_bot[6], h3b[4];
        read_sr(sx, yr0 + k + 2, lc, lane, w_bot);
        #pragma unroll
        for (int i = 0; i < 4; i++)
            h3b[i] = fmax3(w_bot[i], w_bot[i + 1], w_bot[i + 2]);

        float4 o;
        float* op = &o.x;
        #pragma unroll
        for (int i = 0; i < 4; i++) {
            float m = fmax3(h3t[i], fmaxf(w_mid[i], w_mid[i + 2]), h3b[i]);
            m = fmaxf(m, 0.0f);
            const float x = w_mid[i + 1];
            op[i] = (x > m) ? x : 0.0f;
        }
        __stcs((float4*)(oxn + (size_t)(gy0 + k) * W + gx), o);

        #pragma unroll
        for (int i = 0; i < 4; i++) { h3t[i] = h3m[i]; h3m[i] = h3b[i]; }
        #pragma unroll
        for (int j = 0; j < 6; j++) w_mid[j] = w_bot[j];
    }
}

extern "C" void kernel_launch(void* const* d_in, const int* in_sizes, int n_in,
                              void* d_out, int out_size)
{
    const float* seg = (const float*)d_in[0];
    float* out = (float*)d_out;

    dim3 block(TX, TY, 1);
    dim3 grid(W / TILE_W, H / TILE_H, B);  // 8 x 32 x 16 = 4096 CTAs
    detection_head_kernel<<<grid, block>>>(seg, out);
}